// round 6
// baseline (speedup 1.0000x reference)
#include <cuda_runtime.h>

typedef unsigned long long u64;

// ---------------------------------------------------------------------------
// Scratch (device globals -- no allocation allowed)
// ---------------------------------------------------------------------------
__device__ float g_agg[1024 * 64 * 16];    // raw edge aggregation (4 MB)
__device__ float g_Wnb[64 * 64];           // W_n @ W_u_bot
__device__ float g_Weu[16 * 64];           // W_e @ W_u_bot
__device__ float g_cu [64];                // b_m @ W_u_bot + b_u
__device__ unsigned g_ctr;                 // persistent-CTA work counter

// ---------------------------------------------------------------------------
// Packed f32x2 helpers (Blackwell FFMA2 -- only reachable via PTX)
// ---------------------------------------------------------------------------
__device__ __forceinline__ u64 pk2(float lo, float hi) {
    u64 r; asm("mov.b64 %0, {%1, %2};" : "=l"(r) : "f"(lo), "f"(hi)); return r;
}
__device__ __forceinline__ void fma2(u64 &d, u64 a, u64 b) {
    asm("fma.rn.f32x2 %0, %1, %2, %0;" : "+l"(d) : "l"(a), "l"(b));
}
__device__ __forceinline__ void add2(u64 &d, u64 a) {
    asm("add.rn.f32x2 %0, %0, %1;" : "+l"(d) : "l"(a));
}
__device__ __forceinline__ void up2(u64 v, float &lo, float &hi) {
    asm("mov.b64 {%0, %1}, %2;" : "=f"(lo), "=f"(hi) : "l"(v));
}

// ---------------------------------------------------------------------------
// k_edge: per (b,v) raw edge aggregation -> g_agg. One warp per bv, 4 per iter.
// Launched FIRST so ncu (skip L+2) profiles it next round.
// ---------------------------------------------------------------------------
__global__ void __launch_bounds__(256)
k_edge(const int* __restrict__ adj, const float* __restrict__ edges)
{
    int tid = threadIdx.x, w = tid >> 5, lane = tid & 31;
    for (int t = 0; t < 4; t++) {
        int bv = blockIdx.x * 32 + t * 8 + w;
        const int*   arow = adj   + bv * 64;
        const float* erow = edges + (long)bv * 1024;

        float acc[16];
        #pragma unroll
        for (int e = 0; e < 16; e++) acc[e] = 0.f;
        #pragma unroll
        for (int s = 0; s < 2; s++) {
            int u = lane + s * 32;
            if (arow[u] != 0) {
                const float4* e4 = (const float4*)(erow + u * 16);
                float4 x0 = e4[0], x1 = e4[1], x2 = e4[2], x3 = e4[3];
                acc[0] += x0.x;  acc[1] += x0.y;  acc[2]  += x0.z;  acc[3]  += x0.w;
                acc[4] += x1.x;  acc[5] += x1.y;  acc[6]  += x1.z;  acc[7]  += x1.w;
                acc[8] += x2.x;  acc[9] += x2.y;  acc[10] += x2.z;  acc[11] += x2.w;
                acc[12]+= x3.x;  acc[13]+= x3.y;  acc[14] += x3.z;  acc[15] += x3.w;
            }
        }
        #pragma unroll
        for (int off = 16; off > 0; off >>= 1) {
            #pragma unroll
            for (int e = 0; e < 16; e++)
                acc[e] += __shfl_xor_sync(0xffffffffu, acc[e], off);
        }
        if (lane == 0) {
            float4* dst = (float4*)(g_agg + bv * 16);
            dst[0] = make_float4(acc[0],  acc[1],  acc[2],  acc[3]);
            dst[1] = make_float4(acc[4],  acc[5],  acc[6],  acc[7]);
            dst[2] = make_float4(acc[8],  acc[9],  acc[10], acc[11]);
            dst[3] = make_float4(acc[12], acc[13], acc[14], acc[15]);
        }
    }
}

// ---------------------------------------------------------------------------
// k_fold: fold weights (9 blocks) + reset work counter.
// ---------------------------------------------------------------------------
__global__ void __launch_bounds__(256)
k_fold(const float* __restrict__ W_n, const float* __restrict__ W_e,
       const float* __restrict__ b_m, const float* __restrict__ W_u,
       const float* __restrict__ b_u)
{
    __shared__ float s_Wu[128 * 64];
    __shared__ float s_A[16 * 128];
    int tid = threadIdx.x, bx = blockIdx.x;
    for (int i = tid; i < 8192; i += 256) s_Wu[i] = W_u[4096 + i];

    if (bx < 8) {
        int r0 = bx * 8;
        for (int i = tid; i < 1024; i += 256) s_A[i] = W_n[r0 * 128 + i];
        __syncthreads();
        int g = tid & 63, r = tid >> 6;
        for (int rr = r; rr < 8; rr += 4) {
            float acc = 0.f;
            #pragma unroll 8
            for (int m = 0; m < 128; m++)
                acc += s_A[rr * 128 + m] * s_Wu[m * 64 + g];
            g_Wnb[(r0 + rr) * 64 + g] = acc;
        }
    } else {
        if (tid == 0) g_ctr = 0u;
        for (int i = tid; i < 2048; i += 256) s_A[i] = W_e[i];
        __syncthreads();
        int g = tid & 63, r = tid >> 6;
        for (int rr = r; rr < 16; rr += 4) {
            float acc = 0.f;
            #pragma unroll 8
            for (int m = 0; m < 128; m++)
                acc += s_A[rr * 128 + m] * s_Wu[m * 64 + g];
            g_Weu[rr * 64 + g] = acc;
        }
        if (tid < 64) {
            float acc = b_u[tid];
            #pragma unroll 8
            for (int m = 0; m < 128; m++)
                acc += b_m[m] * s_Wu[m * 64 + tid];
            g_cu[tid] = acc;
        }
    }
}

// ---------------------------------------------------------------------------
// k_mpnn: persistent CTAs; 4 passes (f32x2, 2v x 8g tiles) + full readout.
// smem (floats):
//   s_h   [0,4352)       h, stride 68
//   s_W   [4352,12544)   passes: Wu_top|Wnb (f*128); readout: Wr_top, then red
//   s_aT  [12544,16768)  adj transposed, stride 66 | readout: Wr_bot (part 1)
//   s_T   [16768,20864)  T tile / agg-Weu-cu stage | readout: Wr_bot (part 2)
//   s_et  [20864,24960)  et2                        | readout: nodes
//   s_mask[24960,25024)
// total 25024 floats = 100096 B -> 2 CTAs/SM
// ---------------------------------------------------------------------------
#define SMEM_BYTES (25024 * 4)

__global__ void __launch_bounds__(256, 2)
k_mpnn(const int* __restrict__ adj, const float* __restrict__ nodes,
       const float* __restrict__ W_u, const float* __restrict__ W_r,
       const float* __restrict__ b_r, float* __restrict__ out)
{
    extern __shared__ float sm[];
    float* s_h    = sm;
    float* s_W    = sm + 4352;
    float* s_aT   = sm + 12544;
    float* s_T    = sm + 16768;
    float* s_et   = sm + 20864;
    float* s_mask = sm + 24960;
    float* s_Wb   = sm + 12544;   // readout: Wr_bot spans s_aT + s_T (8192)
    float* s_nd   = s_et;         // readout: nodes overlay
    __shared__ unsigned s_b;

    int tid = threadIdx.x;
    const int tx = tid & 7,  ty = tid >> 3;     // passes: 2v x 8g
    const int g0 = tx * 8,   v0 = ty * 2;
    const int rx = tid & 15, ry = tid >> 4;     // readout: 4v x 8o
    const int o0 = rx * 8,   w0 = ry * 4;

    while (true) {
        if (tid == 0) s_b = atomicAdd(&g_ctr, 1u);
        __syncthreads();
        unsigned b = s_b;
        if (b >= 1024u) break;

        // ---- per-batch init ----
        const float* nb = nodes + b * 4096;
        const int*   ab = adj   + b * 4096;
        for (int i4 = tid; i4 < 1024; i4 += 256) {
            int v = i4 >> 4, f = (i4 & 15) * 4;
            float4 hv = *(const float4*)&nb[v * 64 + f];
            *(float4*)&s_h[v * 68 + f] = hv;
            int4 a4 = *(const int4*)&ab[v * 64 + f];
            s_aT[(f + 0) * 66 + v] = (float)a4.x;
            s_aT[(f + 1) * 66 + v] = (float)a4.y;
            s_aT[(f + 2) * 66 + v] = (float)a4.z;
            s_aT[(f + 3) * 66 + v] = (float)a4.w;
        }
        // FIXED (was the R5 bug): cover all 8192 floats of s_W
        for (int i4 = tid; i4 < 2048; i4 += 256) {
            int f = i4 >> 5, gq = (i4 & 31) * 4;
            *(float4*)&s_W[f * 128 + gq] = (gq < 64)
                ? *(const float4*)&W_u[f * 64 + gq]
                : *(const float4*)&g_Wnb[f * 64 + gq - 64];
        }
        // stage agg / Weu / cu into s_T
        for (int i = tid; i < 1024; i += 256) {
            s_T[i]        = g_agg[(long)b * 1024 + i];
            s_T[1024 + i] = g_Weu[i];
        }
        if (tid < 64) s_T[2048 + tid] = g_cu[tid];
        __syncthreads();

        if (tid < 64) {
            float s = 0.f;
            #pragma unroll 8
            for (int u = 0; u < 64; u++) s += s_aT[u * 66 + tid];
            s_mask[tid] = (s > 0.f) ? 1.f : 0.f;
        }
        // et2[v][g] = cu[g] + agg[v][:] @ Weu[:, g]  -> s_et
        {
            float4 c0 = *(const float4*)&s_T[2048 + g0];
            float4 c1 = *(const float4*)&s_T[2048 + g0 + 4];
            #pragma unroll
            for (int i = 0; i < 2; i++) {
                float e0 = c0.x, e1 = c0.y, e2 = c0.z, e3 = c0.w;
                float e4 = c1.x, e5 = c1.y, e6 = c1.z, e7 = c1.w;
                #pragma unroll
                for (int e = 0; e < 16; e++) {
                    float a = s_T[(v0 + i) * 16 + e];
                    float4 u0 = *(const float4*)&s_T[1024 + e * 64 + g0];
                    float4 u1 = *(const float4*)&s_T[1024 + e * 64 + g0 + 4];
                    e0 += a * u0.x; e1 += a * u0.y; e2 += a * u0.z; e3 += a * u0.w;
                    e4 += a * u1.x; e5 += a * u1.y; e6 += a * u1.z; e7 += a * u1.w;
                }
                *(float4*)&s_et[(v0 + i) * 64 + g0]     = make_float4(e0, e1, e2, e3);
                *(float4*)&s_et[(v0 + i) * 64 + g0 + 4] = make_float4(e4, e5, e6, e7);
            }
        }
        __syncthreads();
        float mk0 = s_mask[v0], mk1 = s_mask[v0 + 1];

        // ---- 4 message passes ----
        for (int pass = 0; pass < 4; pass++) {
            // Phase A: G = h@Wu_top (regs), T = h@Wnb (smem)
            u64 G[2][4], T[2][4];
            #pragma unroll
            for (int i = 0; i < 2; i++)
                #pragma unroll
                for (int j = 0; j < 4; j++) { G[i][j] = 0ull; T[i][j] = 0ull; }

            #pragma unroll 4
            for (int f = 0; f < 64; f++) {
                ulonglong2 wg0 = *(const ulonglong2*)&s_W[f * 128 + g0];
                ulonglong2 wg1 = *(const ulonglong2*)&s_W[f * 128 + g0 + 4];
                ulonglong2 wt0 = *(const ulonglong2*)&s_W[f * 128 + 64 + g0];
                ulonglong2 wt1 = *(const ulonglong2*)&s_W[f * 128 + 64 + g0 + 4];
                #pragma unroll
                for (int i = 0; i < 2; i++) {
                    float hv = s_h[(v0 + i) * 68 + f];
                    u64 hp = pk2(hv, hv);
                    fma2(G[i][0], hp, wg0.x); fma2(G[i][1], hp, wg0.y);
                    fma2(G[i][2], hp, wg1.x); fma2(G[i][3], hp, wg1.y);
                    fma2(T[i][0], hp, wt0.x); fma2(T[i][1], hp, wt0.y);
                    fma2(T[i][2], hp, wt1.x); fma2(T[i][3], hp, wt1.y);
                }
            }
            #pragma unroll
            for (int i = 0; i < 2; i++) {
                ulonglong2 a, c;
                a.x = T[i][0]; a.y = T[i][1]; c.x = T[i][2]; c.y = T[i][3];
                *(ulonglong2*)&s_T[(v0 + i) * 64 + g0]     = a;
                *(ulonglong2*)&s_T[(v0 + i) * 64 + g0 + 4] = c;
            }
            __syncthreads();

            // Phase B: S = adj @ T
            u64 S[2][4];
            #pragma unroll
            for (int i = 0; i < 2; i++)
                #pragma unroll
                for (int j = 0; j < 4; j++) S[i][j] = 0ull;

            #pragma unroll 4
            for (int u = 0; u < 64; u++) {
                ulonglong2 t0 = *(const ulonglong2*)&s_T[u * 64 + g0];
                ulonglong2 t1 = *(const ulonglong2*)&s_T[u * 64 + g0 + 4];
                float2 av = *(const float2*)&s_aT[u * 66 + v0];
                u64 a0 = pk2(av.x, av.x), a1 = pk2(av.y, av.y);
                fma2(S[0][0], a0, t0.x); fma2(S[0][1], a0, t0.y);
                fma2(S[0][2], a0, t1.x); fma2(S[0][3], a0, t1.y);
                fma2(S[1][0], a1, t0.x); fma2(S[1][1], a1, t0.y);
                fma2(S[1][2], a1, t1.x); fma2(S[1][3], a1, t1.y);
            }
            // epilogue: h = relu(G + S + et2) where mask, else unchanged
            #pragma unroll
            for (int i = 0; i < 2; i++) {
                float m = (i == 0) ? mk0 : mk1;
                if (m != 0.f) {
                    ulonglong2 e0 = *(const ulonglong2*)&s_et[(v0 + i) * 64 + g0];
                    ulonglong2 e1 = *(const ulonglong2*)&s_et[(v0 + i) * 64 + g0 + 4];
                    add2(G[i][0], S[i][0]); add2(G[i][1], S[i][1]);
                    add2(G[i][2], S[i][2]); add2(G[i][3], S[i][3]);
                    add2(G[i][0], e0.x);    add2(G[i][1], e0.y);
                    add2(G[i][2], e1.x);    add2(G[i][3], e1.y);
                    float x[8];
                    up2(G[i][0], x[0], x[1]); up2(G[i][1], x[2], x[3]);
                    up2(G[i][2], x[4], x[5]); up2(G[i][3], x[6], x[7]);
                    #pragma unroll
                    for (int j = 0; j < 8; j++) x[j] = fmaxf(x[j], 0.f);
                    *(float4*)&s_h[(v0 + i) * 68 + g0]     = make_float4(x[0], x[1], x[2], x[3]);
                    *(float4*)&s_h[(v0 + i) * 68 + g0 + 4] = make_float4(x[4], x[5], x[6], x[7]);
                }
            }
            __syncthreads();
        }

        // ---- readout: out[o] = sum_v mask * relu(h@Wr_top + nodes@Wr_bot + b_r)
        for (int i4 = tid; i4 < 1024; i4 += 256) {
            int v = i4 >> 4, f = (i4 & 15) * 4;
            *(float4*)&s_nd[v * 64 + f] = *(const float4*)&nb[v * 64 + f];
        }
        for (int i4 = tid; i4 < 2048; i4 += 256) {
            *(float4*)&s_W [i4 * 4] = *(const float4*)&W_r[i4 * 4];          // top
            *(float4*)&s_Wb[i4 * 4] = *(const float4*)&W_r[8192 + i4 * 4];   // bot
        }
        __syncthreads();

        u64 acc[4][4];
        {
            ulonglong2 br0 = *(const ulonglong2*)&b_r[o0];
            ulonglong2 br1 = *(const ulonglong2*)&b_r[o0 + 4];
            #pragma unroll
            for (int i = 0; i < 4; i++) {
                acc[i][0] = br0.x; acc[i][1] = br0.y;
                acc[i][2] = br1.x; acc[i][3] = br1.y;
            }
        }
        #pragma unroll 2
        for (int k = 0; k < 64; k++) {
            ulonglong2 q0 = *(const ulonglong2*)&s_W[k * 128 + o0];
            ulonglong2 q1 = *(const ulonglong2*)&s_W[k * 128 + o0 + 4];
            #pragma unroll
            for (int i = 0; i < 4; i++) {
                float hv = s_h[(w0 + i) * 68 + k];
                u64 hp = pk2(hv, hv);
                fma2(acc[i][0], hp, q0.x); fma2(acc[i][1], hp, q0.y);
                fma2(acc[i][2], hp, q1.x); fma2(acc[i][3], hp, q1.y);
            }
        }
        #pragma unroll 2
        for (int k = 0; k < 64; k++) {
            ulonglong2 q0 = *(const ulonglong2*)&s_Wb[k * 128 + o0];
            ulonglong2 q1 = *(const ulonglong2*)&s_Wb[k * 128 + o0 + 4];
            #pragma unroll
            for (int i = 0; i < 4; i++) {
                float nv = s_nd[(w0 + i) * 64 + k];
                u64 np = pk2(nv, nv);
                fma2(acc[i][0], np, q0.x); fma2(acc[i][1], np, q0.y);
                fma2(acc[i][2], np, q1.x); fma2(acc[i][3], np, q1.y);
            }
        }
        float oa[8];
        #pragma unroll
        for (int j = 0; j < 8; j++) oa[j] = 0.f;
        #pragma unroll
        for (int i = 0; i < 4; i++) {
            if (s_mask[w0 + i] != 0.f) {
                float x[8];
                up2(acc[i][0], x[0], x[1]); up2(acc[i][1], x[2], x[3]);
                up2(acc[i][2], x[4], x[5]); up2(acc[i][3], x[6], x[7]);
                #pragma unroll
                for (int j = 0; j < 8; j++) oa[j] += fmaxf(x[j], 0.f);
            }
        }
        __syncthreads();   // s_W reads done; reuse as reduction buffer
        *(float4*)&s_W[ry * 128 + o0]     = make_float4(oa[0], oa[1], oa[2], oa[3]);
        *(float4*)&s_W[ry * 128 + o0 + 4] = make_float4(oa[4], oa[5], oa[6], oa[7]);
        __syncthreads();
        if (tid < 128) {
            float s = 0.f;
            #pragma unroll
            for (int t = 0; t < 16; t++) s += s_W[t * 128 + tid];
            out[b * 128 + tid] = s;
        }
        __syncthreads();
    }
}

// ---------------------------------------------------------------------------
// Launch
// ---------------------------------------------------------------------------
extern "C" void kernel_launch(void* const* d_in, const int* in_sizes, int n_in,
                              void* d_out, int out_size)
{
    const int*   adj   = (const int*)  d_in[0];
    const float* nodes = (const float*)d_in[1];
    const float* edges = (const float*)d_in[2];
    const float* W_n   = (const float*)d_in[3];
    const float* W_e   = (const float*)d_in[4];
    const float* b_m   = (const float*)d_in[5];
    const float* W_u   = (const float*)d_in[6];
    const float* b_u   = (const float*)d_in[7];
    const float* W_r   = (const float*)d_in[8];
    const float* b_r   = (const float*)d_in[9];
    float* out = (float*)d_out;

    cudaFuncSetAttribute(k_mpnn, cudaFuncAttributeMaxDynamicSharedMemorySize,
                         SMEM_BYTES);

    k_edge<<<2048, 256>>>(adj, edges);
    k_fold<<<9, 256>>>(W_n, W_e, b_m, W_u, b_u);
    k_mpnn<<<296, 256, SMEM_BYTES>>>(adj, nodes, W_u, W_r, b_r, out);
}

// round 7
// speedup vs baseline: 1.9481x; 1.9481x over previous
#include <cuda_runtime.h>

typedef unsigned long long u64;

// ---------------------------------------------------------------------------
// Scratch (device globals -- no allocation allowed)
// ---------------------------------------------------------------------------
__device__ float g_agg[1024 * 64 * 16];    // raw edge aggregation (4 MB)
__device__ float g_Wnb[64 * 64];           // W_n @ W_u_bot
__device__ float g_Weu[16 * 64];           // W_e @ W_u_bot
__device__ float g_cu [64];                // b_m @ W_u_bot + b_u
__device__ unsigned g_ctr;                 // persistent-CTA work counter

// ---------------------------------------------------------------------------
// Packed f32x2 helpers (Blackwell FFMA2 -- only reachable via PTX)
// ---------------------------------------------------------------------------
__device__ __forceinline__ u64 pk2(float lo, float hi) {
    u64 r; asm("mov.b64 %0, {%1, %2};" : "=l"(r) : "f"(lo), "f"(hi)); return r;
}
__device__ __forceinline__ void fma2(u64 &d, u64 a, u64 b) {
    asm("fma.rn.f32x2 %0, %1, %2, %0;" : "+l"(d) : "l"(a), "l"(b));
}
__device__ __forceinline__ void add2(u64 &d, u64 a) {
    asm("add.rn.f32x2 %0, %0, %1;" : "+l"(d) : "l"(a));
}
__device__ __forceinline__ void up2(u64 v, float &lo, float &hi) {
    asm("mov.b64 {%0, %1}, %2;" : "=f"(lo), "=f"(hi) : "l"(v));
}

// ---------------------------------------------------------------------------
// k_pre: role-split grid.
//  blocks 0..2047 : per (b,v) raw edge aggregation -> g_agg (measured 48.6us)
//  blocks 2048..2056 : weight folds + counter reset
// ---------------------------------------------------------------------------
__global__ void __launch_bounds__(256)
k_pre(const int* __restrict__ adj, const float* __restrict__ edges,
      const float* __restrict__ W_n, const float* __restrict__ W_e,
      const float* __restrict__ b_m, const float* __restrict__ W_u,
      const float* __restrict__ b_u)
{
    __shared__ float buf[10240];   // 40 KB, used by fold blocks only
    int bx = blockIdx.x, tid = threadIdx.x;

    if (bx < 2048) {
        int w = tid >> 5, lane = tid & 31;
        for (int t = 0; t < 4; t++) {
            int bv = bx * 32 + t * 8 + w;
            const int*   arow = adj   + bv * 64;
            const float* erow = edges + (long)bv * 1024;

            float acc[16];
            #pragma unroll
            for (int e = 0; e < 16; e++) acc[e] = 0.f;
            #pragma unroll
            for (int s = 0; s < 2; s++) {
                int u = lane + s * 32;
                if (arow[u] != 0) {
                    const float4* e4 = (const float4*)(erow + u * 16);
                    float4 x0 = e4[0], x1 = e4[1], x2 = e4[2], x3 = e4[3];
                    acc[0] += x0.x;  acc[1] += x0.y;  acc[2]  += x0.z;  acc[3]  += x0.w;
                    acc[4] += x1.x;  acc[5] += x1.y;  acc[6]  += x1.z;  acc[7]  += x1.w;
                    acc[8] += x2.x;  acc[9] += x2.y;  acc[10] += x2.z;  acc[11] += x2.w;
                    acc[12]+= x3.x;  acc[13]+= x3.y;  acc[14] += x3.z;  acc[15] += x3.w;
                }
            }
            #pragma unroll
            for (int off = 16; off > 0; off >>= 1) {
                #pragma unroll
                for (int e = 0; e < 16; e++)
                    acc[e] += __shfl_xor_sync(0xffffffffu, acc[e], off);
            }
            if (lane == 0) {
                float4* dst = (float4*)(g_agg + bv * 16);
                dst[0] = make_float4(acc[0],  acc[1],  acc[2],  acc[3]);
                dst[1] = make_float4(acc[4],  acc[5],  acc[6],  acc[7]);
                dst[2] = make_float4(acc[8],  acc[9],  acc[10], acc[11]);
                dst[3] = make_float4(acc[12], acc[13], acc[14], acc[15]);
            }
        }
    } else {
        float* s_Wu = buf;                 // W_u bottom rows (8192)
        float* s_A  = buf + 8192;          // operand rows (<=2048)
        for (int i = tid; i < 8192; i += 256) s_Wu[i] = W_u[4096 + i];

        if (bx < 2056) {                   // Wnb rows (bx-2048)*8 ..+8
            int r0 = (bx - 2048) * 8;
            for (int i = tid; i < 1024; i += 256) s_A[i] = W_n[r0 * 128 + i];
            __syncthreads();
            int g = tid & 63, r = tid >> 6;
            for (int rr = r; rr < 8; rr += 4) {
                float acc = 0.f;
                #pragma unroll 8
                for (int m = 0; m < 128; m++)
                    acc += s_A[rr * 128 + m] * s_Wu[m * 64 + g];
                g_Wnb[(r0 + rr) * 64 + g] = acc;
            }
        } else {                           // Weu + cu + ctr
            if (tid == 0) g_ctr = 0u;
            for (int i = tid; i < 2048; i += 256) s_A[i] = W_e[i];
            __syncthreads();
            int g = tid & 63, r = tid >> 6;
            for (int rr = r; rr < 16; rr += 4) {
                float acc = 0.f;
                #pragma unroll 8
                for (int m = 0; m < 128; m++)
                    acc += s_A[rr * 128 + m] * s_Wu[m * 64 + g];
                g_Weu[rr * 64 + g] = acc;
            }
            if (tid < 64) {
                float acc = b_u[tid];
                #pragma unroll 8
                for (int m = 0; m < 128; m++)
                    acc += b_m[m] * s_Wu[m * 64 + tid];
                g_cu[tid] = acc;
            }
        }
    }
}

// ---------------------------------------------------------------------------
// k_mpnn: persistent CTAs; 4 passes (f32x2, 4v x 4g tiles, h TRANSPOSED) +
// full readout. smem (floats):
//   s_hT  [0,4352)       h transposed [f*68 + v]
//   s_W   [4352,12544)   passes: Wu_top|Wnb (f*128); readout: Wr_top, then red
//   s_aT  [12544,16896)  adj transposed [u*68 + v] | readout: Wr_bot (part 1)
//   s_T   [16896,20992)  T tile / agg-Weu-cu stage | readout: Wr_bot (part 2)
//   s_et  [20992,25088)  et2                       | readout: nT [f*68+v]
//   (nT overlay spans [20992,25344))
//   s_mask[25344,25408)
// total 25408 floats = 101632 B -> 2 CTAs/SM
// ---------------------------------------------------------------------------
#define SMEM_BYTES (25408 * 4)

__global__ void __launch_bounds__(256, 2)
k_mpnn(const int* __restrict__ adj, const float* __restrict__ nodes,
       const float* __restrict__ W_u, const float* __restrict__ W_r,
       const float* __restrict__ b_r, float* __restrict__ out)
{
    extern __shared__ float sm[];
    float* s_hT   = sm;
    float* s_W    = sm + 4352;
    float* s_aT   = sm + 12544;
    float* s_T    = sm + 16896;
    float* s_et   = sm + 20992;
    float* s_mask = sm + 25344;
    float* s_Wrb  = sm + 12544;   // readout overlay (8192, spans aT+T)
    float* s_nT   = sm + 20992;   // readout overlay (4352, spans et+)
    float* s_red  = s_W;          // readout reduction overlay
    __shared__ unsigned s_b;

    int tid = threadIdx.x;
    const int tx = tid & 15, ty = tid >> 4;     // passes: 4v x 4g
    const int g0 = tx * 4,   v0 = ty * 4;
    const int rx = tid & 31, ry = tid >> 5;     // readout: 8v x 4o
    const int o0 = rx * 4,   v0r = ry * 8;

    while (true) {
        if (tid == 0) s_b = atomicAdd(&g_ctr, 1u);
        __syncthreads();
        unsigned b = s_b;
        if (b >= 1024u) break;

        // ---- per-batch staging ----
        const float* nb = nodes + b * 4096;
        const int*   ab = adj   + b * 4096;
        for (int i4 = tid; i4 < 1024; i4 += 256) {
            int v = i4 >> 4, f = (i4 & 15) * 4;
            float4 hv = *(const float4*)&nb[v * 64 + f];
            s_hT[(f + 0) * 68 + v] = hv.x;
            s_hT[(f + 1) * 68 + v] = hv.y;
            s_hT[(f + 2) * 68 + v] = hv.z;
            s_hT[(f + 3) * 68 + v] = hv.w;
            int4 a4 = *(const int4*)&ab[v * 64 + f];
            s_aT[(f + 0) * 68 + v] = (float)a4.x;
            s_aT[(f + 1) * 68 + v] = (float)a4.y;
            s_aT[(f + 2) * 68 + v] = (float)a4.z;
            s_aT[(f + 3) * 68 + v] = (float)a4.w;
        }
        for (int i4 = tid; i4 < 2048; i4 += 256) {
            int f = i4 >> 5, gq = (i4 & 31) * 4;
            *(float4*)&s_W[f * 128 + gq] = (gq < 64)
                ? *(const float4*)&W_u[f * 64 + gq]
                : *(const float4*)&g_Wnb[f * 64 + gq - 64];
        }
        for (int i = tid; i < 1024; i += 256) {
            s_T[i]        = g_agg[(long)b * 1024 + i];
            s_T[1024 + i] = g_Weu[i];
        }
        if (tid < 64) s_T[2048 + tid] = g_cu[tid];
        __syncthreads();

        if (tid < 64) {
            float s = 0.f;
            #pragma unroll 8
            for (int u = 0; u < 64; u++) s += s_aT[u * 68 + tid];
            s_mask[tid] = (s > 0.f) ? 1.f : 0.f;
        }
        // et2[v][g] = cu[g] + agg[v][:] @ Weu[:, g]  -> s_et
        {
            float4 cu4 = *(const float4*)&s_T[2048 + g0];
            #pragma unroll
            for (int i = 0; i < 4; i++) {
                float e0 = cu4.x, e1 = cu4.y, e2 = cu4.z, e3 = cu4.w;
                #pragma unroll
                for (int e = 0; e < 16; e++) {
                    float a = s_T[(v0 + i) * 16 + e];
                    float4 u4 = *(const float4*)&s_T[1024 + e * 64 + g0];
                    e0 += a * u4.x; e1 += a * u4.y; e2 += a * u4.z; e3 += a * u4.w;
                }
                *(float4*)&s_et[(v0 + i) * 64 + g0] = make_float4(e0, e1, e2, e3);
            }
        }
        __syncthreads();
        float mk[4];
        #pragma unroll
        for (int i = 0; i < 4; i++) mk[i] = s_mask[v0 + i];

        // ---- 4 message passes ----
        for (int pass = 0; pass < 4; pass++) {
            // Phase A: G = h@Wu_top (regs), T = h@Wnb (smem); h read via hT
            u64 G[4][2], T[4][2];
            #pragma unroll
            for (int i = 0; i < 4; i++) {
                G[i][0] = 0ull; G[i][1] = 0ull;
                T[i][0] = 0ull; T[i][1] = 0ull;
            }
            #pragma unroll 4
            for (int f = 0; f < 64; f++) {
                ulonglong2 wg = *(const ulonglong2*)&s_W[f * 128 + g0];
                ulonglong2 wt = *(const ulonglong2*)&s_W[f * 128 + 64 + g0];
                float4 hv = *(const float4*)&s_hT[f * 68 + v0];
                u64 hp;
                hp = pk2(hv.x, hv.x);
                fma2(G[0][0], hp, wg.x); fma2(G[0][1], hp, wg.y);
                fma2(T[0][0], hp, wt.x); fma2(T[0][1], hp, wt.y);
                hp = pk2(hv.y, hv.y);
                fma2(G[1][0], hp, wg.x); fma2(G[1][1], hp, wg.y);
                fma2(T[1][0], hp, wt.x); fma2(T[1][1], hp, wt.y);
                hp = pk2(hv.z, hv.z);
                fma2(G[2][0], hp, wg.x); fma2(G[2][1], hp, wg.y);
                fma2(T[2][0], hp, wt.x); fma2(T[2][1], hp, wt.y);
                hp = pk2(hv.w, hv.w);
                fma2(G[3][0], hp, wg.x); fma2(G[3][1], hp, wg.y);
                fma2(T[3][0], hp, wt.x); fma2(T[3][1], hp, wt.y);
            }
            #pragma unroll
            for (int i = 0; i < 4; i++) {
                ulonglong2 tv; tv.x = T[i][0]; tv.y = T[i][1];
                *(ulonglong2*)&s_T[(v0 + i) * 64 + g0] = tv;
            }
            __syncthreads();

            // Phase B: S = adj @ T
            u64 S[4][2];
            #pragma unroll
            for (int i = 0; i < 4; i++) { S[i][0] = 0ull; S[i][1] = 0ull; }
            #pragma unroll 4
            for (int u = 0; u < 64; u++) {
                ulonglong2 tp = *(const ulonglong2*)&s_T[u * 64 + g0];
                float4 av = *(const float4*)&s_aT[u * 68 + v0];
                u64 a;
                a = pk2(av.x, av.x); fma2(S[0][0], a, tp.x); fma2(S[0][1], a, tp.y);
                a = pk2(av.y, av.y); fma2(S[1][0], a, tp.x); fma2(S[1][1], a, tp.y);
                a = pk2(av.z, av.z); fma2(S[2][0], a, tp.x); fma2(S[2][1], a, tp.y);
                a = pk2(av.w, av.w); fma2(S[3][0], a, tp.x); fma2(S[3][1], a, tp.y);
            }
            // epilogue: x = relu(G + S + et2); hT <- mask ? x : old
            float x[4][4];
            #pragma unroll
            for (int i = 0; i < 4; i++) {
                ulonglong2 e = *(const ulonglong2*)&s_et[(v0 + i) * 64 + g0];
                add2(G[i][0], S[i][0]); add2(G[i][1], S[i][1]);
                add2(G[i][0], e.x);     add2(G[i][1], e.y);
                up2(G[i][0], x[i][0], x[i][1]);
                up2(G[i][1], x[i][2], x[i][3]);
                x[i][0] = fmaxf(x[i][0], 0.f); x[i][1] = fmaxf(x[i][1], 0.f);
                x[i][2] = fmaxf(x[i][2], 0.f); x[i][3] = fmaxf(x[i][3], 0.f);
            }
            #pragma unroll
            for (int j = 0; j < 4; j++) {
                float4 old = *(const float4*)&s_hT[(g0 + j) * 68 + v0];
                float4 nv;
                nv.x = (mk[0] != 0.f) ? x[0][j] : old.x;
                nv.y = (mk[1] != 0.f) ? x[1][j] : old.y;
                nv.z = (mk[2] != 0.f) ? x[2][j] : old.z;
                nv.w = (mk[3] != 0.f) ? x[3][j] : old.w;
                *(float4*)&s_hT[(g0 + j) * 68 + v0] = nv;
            }
            __syncthreads();
        }

        // ---- readout: out[o] = sum_v mask * relu(h@Wr_top + nodes@Wr_bot + b_r)
        for (int i4 = tid; i4 < 2048; i4 += 256) {
            *(float4*)&s_W  [i4 * 4] = *(const float4*)&W_r[i4 * 4];          // top
            *(float4*)&s_Wrb[i4 * 4] = *(const float4*)&W_r[8192 + i4 * 4];   // bot
        }
        for (int i4 = tid; i4 < 1024; i4 += 256) {
            int v = i4 >> 4, f = (i4 & 15) * 4;
            float4 nv = *(const float4*)&nb[v * 64 + f];
            s_nT[(f + 0) * 68 + v] = nv.x;
            s_nT[(f + 1) * 68 + v] = nv.y;
            s_nT[(f + 2) * 68 + v] = nv.z;
            s_nT[(f + 3) * 68 + v] = nv.w;
        }
        __syncthreads();

        u64 acc[8][2];
        {
            ulonglong2 br = *(const ulonglong2*)&b_r[o0];
            #pragma unroll
            for (int vv = 0; vv < 8; vv++) { acc[vv][0] = br.x; acc[vv][1] = br.y; }
        }
        #pragma unroll 2
        for (int k = 0; k < 64; k++) {
            ulonglong2 q = *(const ulonglong2*)&s_W[k * 128 + o0];
            float4 h0 = *(const float4*)&s_hT[k * 68 + v0r];
            float4 h1 = *(const float4*)&s_hT[k * 68 + v0r + 4];
            u64 hp;
            hp = pk2(h0.x, h0.x); fma2(acc[0][0], hp, q.x); fma2(acc[0][1], hp, q.y);
            hp = pk2(h0.y, h0.y); fma2(acc[1][0], hp, q.x); fma2(acc[1][1], hp, q.y);
            hp = pk2(h0.z, h0.z); fma2(acc[2][0], hp, q.x); fma2(acc[2][1], hp, q.y);
            hp = pk2(h0.w, h0.w); fma2(acc[3][0], hp, q.x); fma2(acc[3][1], hp, q.y);
            hp = pk2(h1.x, h1.x); fma2(acc[4][0], hp, q.x); fma2(acc[4][1], hp, q.y);
            hp = pk2(h1.y, h1.y); fma2(acc[5][0], hp, q.x); fma2(acc[5][1], hp, q.y);
            hp = pk2(h1.z, h1.z); fma2(acc[6][0], hp, q.x); fma2(acc[6][1], hp, q.y);
            hp = pk2(h1.w, h1.w); fma2(acc[7][0], hp, q.x); fma2(acc[7][1], hp, q.y);
        }
        #pragma unroll 2
        for (int k = 0; k < 64; k++) {
            ulonglong2 q = *(const ulonglong2*)&s_Wrb[k * 128 + o0];
            float4 n0 = *(const float4*)&s_nT[k * 68 + v0r];
            float4 n1 = *(const float4*)&s_nT[k * 68 + v0r + 4];
            u64 hp;
            hp = pk2(n0.x, n0.x); fma2(acc[0][0], hp, q.x); fma2(acc[0][1], hp, q.y);
            hp = pk2(n0.y, n0.y); fma2(acc[1][0], hp, q.x); fma2(acc[1][1], hp, q.y);
            hp = pk2(n0.z, n0.z); fma2(acc[2][0], hp, q.x); fma2(acc[2][1], hp, q.y);
            hp = pk2(n0.w, n0.w); fma2(acc[3][0], hp, q.x); fma2(acc[3][1], hp, q.y);
            hp = pk2(n1.x, n1.x); fma2(acc[4][0], hp, q.x); fma2(acc[4][1], hp, q.y);
            hp = pk2(n1.y, n1.y); fma2(acc[5][0], hp, q.x); fma2(acc[5][1], hp, q.y);
            hp = pk2(n1.z, n1.z); fma2(acc[6][0], hp, q.x); fma2(acc[6][1], hp, q.y);
            hp = pk2(n1.w, n1.w); fma2(acc[7][0], hp, q.x); fma2(acc[7][1], hp, q.y);
        }
        float oa[4] = {0.f, 0.f, 0.f, 0.f};
        #pragma unroll
        for (int vv = 0; vv < 8; vv++) {
            if (s_mask[v0r + vv] != 0.f) {
                float y0, y1, y2, y3;
                up2(acc[vv][0], y0, y1); up2(acc[vv][1], y2, y3);
                oa[0] += fmaxf(y0, 0.f); oa[1] += fmaxf(y1, 0.f);
                oa[2] += fmaxf(y2, 0.f); oa[3] += fmaxf(y3, 0.f);
            }
        }
        __syncthreads();   // s_W reads done; reuse as reduction buffer
        *(float4*)&s_red[ry * 128 + o0] = make_float4(oa[0], oa[1], oa[2], oa[3]);
        __syncthreads();
        if (tid < 128) {
            float s = 0.f;
            #pragma unroll
            for (int t = 0; t < 8; t++) s += s_red[t * 128 + tid];
            out[b * 128 + tid] = s;
        }
        __syncthreads();
    }
}

// ---------------------------------------------------------------------------
// Launch
// ---------------------------------------------------------------------------
extern "C" void kernel_launch(void* const* d_in, const int* in_sizes, int n_in,
                              void* d_out, int out_size)
{
    const int*   adj   = (const int*)  d_in[0];
    const float* nodes = (const float*)d_in[1];
    const float* edges = (const float*)d_in[2];
    const float* W_n   = (const float*)d_in[3];
    const float* W_e   = (const float*)d_in[4];
    const float* b_m   = (const float*)d_in[5];
    const float* W_u   = (const float*)d_in[6];
    const float* b_u   = (const float*)d_in[7];
    const float* W_r   = (const float*)d_in[8];
    const float* b_r   = (const float*)d_in[9];
    float* out = (float*)d_out;

    cudaFuncSetAttribute(k_mpnn, cudaFuncAttributeMaxDynamicSharedMemorySize,
                         SMEM_BYTES);

    k_pre<<<2057, 256>>>(adj, edges, W_n, W_e, b_m, W_u, b_u);
    k_mpnn<<<296, 256, SMEM_BYTES>>>(adj, nodes, W_u, W_r, b_r, out);
}

// round 8
// speedup vs baseline: 1.9551x; 1.0036x over previous
#include <cuda_runtime.h>

typedef unsigned long long u64;

// ---------------------------------------------------------------------------
// Scratch (device globals -- no allocation allowed)
// ---------------------------------------------------------------------------
__device__ float g_Wnb[64 * 64];           // W_n @ W_u_bot
__device__ float g_Weu[16 * 64];           // W_e @ W_u_bot
__device__ float g_cu [64];                // b_m @ W_u_bot + b_u
__device__ unsigned g_ctr;                 // persistent-CTA work counter

// ---------------------------------------------------------------------------
// Packed f32x2 helpers (Blackwell FFMA2 -- only reachable via PTX)
// ---------------------------------------------------------------------------
__device__ __forceinline__ u64 pk2(float lo, float hi) {
    u64 r; asm("mov.b64 %0, {%1, %2};" : "=l"(r) : "f"(lo), "f"(hi)); return r;
}
__device__ __forceinline__ void fma2(u64 &d, u64 a, u64 b) {
    asm("fma.rn.f32x2 %0, %1, %2, %0;" : "+l"(d) : "l"(a), "l"(b));
}
__device__ __forceinline__ void add2(u64 &d, u64 a) {
    asm("add.rn.f32x2 %0, %0, %1;" : "+l"(d) : "l"(a));
}
__device__ __forceinline__ void up2(u64 v, float &lo, float &hi) {
    asm("mov.b64 {%0, %1}, %2;" : "=f"(lo), "=f"(hi) : "l"(v));
}

// ---------------------------------------------------------------------------
// k_fold: fold weights (9 blocks) + reset work counter. (proven in R6)
// ---------------------------------------------------------------------------
__global__ void __launch_bounds__(256)
k_fold(const float* __restrict__ W_n, const float* __restrict__ W_e,
       const float* __restrict__ b_m, const float* __restrict__ W_u,
       const float* __restrict__ b_u)
{
    __shared__ float s_Wu[128 * 64];
    __shared__ float s_A[16 * 128];
    int tid = threadIdx.x, bx = blockIdx.x;
    for (int i = tid; i < 8192; i += 256) s_Wu[i] = W_u[4096 + i];

    if (bx < 8) {
        int r0 = bx * 8;
        for (int i = tid; i < 1024; i += 256) s_A[i] = W_n[r0 * 128 + i];
        __syncthreads();
        int g = tid & 63, r = tid >> 6;
        for (int rr = r; rr < 8; rr += 4) {
            float acc = 0.f;
            #pragma unroll 8
            for (int m = 0; m < 128; m++)
                acc += s_A[rr * 128 + m] * s_Wu[m * 64 + g];
            g_Wnb[(r0 + rr) * 64 + g] = acc;
        }
    } else {
        if (tid == 0) g_ctr = 0u;
        for (int i = tid; i < 2048; i += 256) s_A[i] = W_e[i];
        __syncthreads();
        int g = tid & 63, r = tid >> 6;
        for (int rr = r; rr < 16; rr += 4) {
            float acc = 0.f;
            #pragma unroll 8
            for (int m = 0; m < 128; m++)
                acc += s_A[rr * 128 + m] * s_Wu[m * 64 + g];
            g_Weu[rr * 64 + g] = acc;
        }
        if (tid < 64) {
            float acc = b_u[tid];
            #pragma unroll 8
            for (int m = 0; m < 128; m++)
                acc += b_m[m] * s_Wu[m * 64 + tid];
            g_cu[tid] = acc;
        }
    }
}

// ---------------------------------------------------------------------------
// k_mpnn: persistent CTAs. Per batch: INLINE edge aggregation (overlaps other
// CTAs' compute), et2, 4 passes (f32x2, 4v x 4g, h transposed), full readout.
// smem layout identical to R7 (25408 floats = 101632 B -> 2 CTAs/SM).
// ---------------------------------------------------------------------------
#define SMEM_BYTES (25408 * 4)

__global__ void __launch_bounds__(256, 2)
k_mpnn(const int* __restrict__ adj, const float* __restrict__ nodes,
       const float* __restrict__ edges,
       const float* __restrict__ W_u, const float* __restrict__ W_r,
       const float* __restrict__ b_r, float* __restrict__ out)
{
    extern __shared__ float sm[];
    float* s_hT   = sm;
    float* s_W    = sm + 4352;
    float* s_aT   = sm + 12544;
    float* s_T    = sm + 16896;
    float* s_et   = sm + 20992;
    float* s_mask = sm + 25344;
    float* s_Wrb  = sm + 12544;   // readout overlay (8192, spans aT+T)
    float* s_nT   = sm + 20992;   // readout overlay (4352, spans et+)
    float* s_red  = s_W;          // readout reduction overlay
    __shared__ unsigned s_b;

    int tid = threadIdx.x;
    const int w = tid >> 5, lane = tid & 31;
    const int tx = tid & 15, ty = tid >> 4;     // passes: 4v x 4g
    const int g0 = tx * 4,   v0 = ty * 4;
    const int rx = tid & 31, ry = tid >> 5;     // readout: 8v x 4o
    const int o0 = rx * 4,   v0r = ry * 8;

    while (true) {
        if (tid == 0) s_b = atomicAdd(&g_ctr, 1u);
        __syncthreads();
        unsigned b = s_b;
        if (b >= 1024u) break;

        // ---- per-batch staging ----
        const float* nb = nodes + b * 4096;
        const int*   ab = adj   + b * 4096;
        const float* eb = edges + (long)b * 65536;
        for (int i4 = tid; i4 < 1024; i4 += 256) {
            int v = i4 >> 4, f = (i4 & 15) * 4;
            float4 hv = *(const float4*)&nb[v * 64 + f];
            s_hT[(f + 0) * 68 + v] = hv.x;
            s_hT[(f + 1) * 68 + v] = hv.y;
            s_hT[(f + 2) * 68 + v] = hv.z;
            s_hT[(f + 3) * 68 + v] = hv.w;
            int4 a4 = *(const int4*)&ab[v * 64 + f];
            s_aT[(f + 0) * 68 + v] = (float)a4.x;
            s_aT[(f + 1) * 68 + v] = (float)a4.y;
            s_aT[(f + 2) * 68 + v] = (float)a4.z;
            s_aT[(f + 3) * 68 + v] = (float)a4.w;
        }
        for (int i4 = tid; i4 < 2048; i4 += 256) {
            int f = i4 >> 5, gq = (i4 & 31) * 4;
            *(float4*)&s_W[f * 128 + gq] = (gq < 64)
                ? *(const float4*)&W_u[f * 64 + gq]
                : *(const float4*)&g_Wnb[f * 64 + gq - 64];
        }
        for (int i = tid; i < 1024; i += 256) s_T[1024 + i] = g_Weu[i];
        if (tid < 64) s_T[2048 + tid] = g_cu[tid];
        __syncthreads();

        // mask (warps 0-1) + INLINE edge aggregation (all 8 warps, 8 nodes ea)
        if (tid < 64) {
            float s = 0.f;
            #pragma unroll 8
            for (int u = 0; u < 64; u++) s += s_aT[u * 68 + tid];
            s_mask[tid] = (s > 0.f) ? 1.f : 0.f;
        }
        for (int t = 0; t < 8; t++) {
            int v = w * 8 + t;
            const int*   arow = ab + v * 64;
            const float* erow = eb + v * 1024;
            float acc[16];
            #pragma unroll
            for (int e = 0; e < 16; e++) acc[e] = 0.f;
            #pragma unroll
            for (int s = 0; s < 2; s++) {
                int u = lane + s * 32;
                if (arow[u] != 0) {
                    const float4* e4 = (const float4*)(erow + u * 16);
                    float4 x0 = e4[0], x1 = e4[1], x2 = e4[2], x3 = e4[3];
                    acc[0] += x0.x;  acc[1] += x0.y;  acc[2]  += x0.z;  acc[3]  += x0.w;
                    acc[4] += x1.x;  acc[5] += x1.y;  acc[6]  += x1.z;  acc[7]  += x1.w;
                    acc[8] += x2.x;  acc[9] += x2.y;  acc[10] += x2.z;  acc[11] += x2.w;
                    acc[12]+= x3.x;  acc[13]+= x3.y;  acc[14] += x3.z;  acc[15] += x3.w;
                }
            }
            #pragma unroll
            for (int off = 16; off > 0; off >>= 1) {
                #pragma unroll
                for (int e = 0; e < 16; e++)
                    acc[e] += __shfl_xor_sync(0xffffffffu, acc[e], off);
            }
            if (lane == 0) {
                float4* dst = (float4*)&s_T[v * 16];
                dst[0] = make_float4(acc[0],  acc[1],  acc[2],  acc[3]);
                dst[1] = make_float4(acc[4],  acc[5],  acc[6],  acc[7]);
                dst[2] = make_float4(acc[8],  acc[9],  acc[10], acc[11]);
                dst[3] = make_float4(acc[12], acc[13], acc[14], acc[15]);
            }
        }
        __syncthreads();

        // et2[v][g] = cu[g] + agg[v][:] @ Weu[:, g]  -> s_et
        {
            float4 cu4 = *(const float4*)&s_T[2048 + g0];
            #pragma unroll
            for (int i = 0; i < 4; i++) {
                float e0 = cu4.x, e1 = cu4.y, e2 = cu4.z, e3 = cu4.w;
                #pragma unroll
                for (int e = 0; e < 16; e++) {
                    float a = s_T[(v0 + i) * 16 + e];
                    float4 u4 = *(const float4*)&s_T[1024 + e * 64 + g0];
                    e0 += a * u4.x; e1 += a * u4.y; e2 += a * u4.z; e3 += a * u4.w;
                }
                *(float4*)&s_et[(v0 + i) * 64 + g0] = make_float4(e0, e1, e2, e3);
            }
        }
        __syncthreads();
        float mk[4];
        #pragma unroll
        for (int i = 0; i < 4; i++) mk[i] = s_mask[v0 + i];

        // ---- 4 message passes (identical to R7) ----
        for (int pass = 0; pass < 4; pass++) {
            u64 G[4][2], T[4][2];
            #pragma unroll
            for (int i = 0; i < 4; i++) {
                G[i][0] = 0ull; G[i][1] = 0ull;
                T[i][0] = 0ull; T[i][1] = 0ull;
            }
            #pragma unroll 4
            for (int f = 0; f < 64; f++) {
                ulonglong2 wg = *(const ulonglong2*)&s_W[f * 128 + g0];
                ulonglong2 wt = *(const ulonglong2*)&s_W[f * 128 + 64 + g0];
                float4 hv = *(const float4*)&s_hT[f * 68 + v0];
                u64 hp;
                hp = pk2(hv.x, hv.x);
                fma2(G[0][0], hp, wg.x); fma2(G[0][1], hp, wg.y);
                fma2(T[0][0], hp, wt.x); fma2(T[0][1], hp, wt.y);
                hp = pk2(hv.y, hv.y);
                fma2(G[1][0], hp, wg.x); fma2(G[1][1], hp, wg.y);
                fma2(T[1][0], hp, wt.x); fma2(T[1][1], hp, wt.y);
                hp = pk2(hv.z, hv.z);
                fma2(G[2][0], hp, wg.x); fma2(G[2][1], hp, wg.y);
                fma2(T[2][0], hp, wt.x); fma2(T[2][1], hp, wt.y);
                hp = pk2(hv.w, hv.w);
                fma2(G[3][0], hp, wg.x); fma2(G[3][1], hp, wg.y);
                fma2(T[3][0], hp, wt.x); fma2(T[3][1], hp, wt.y);
            }
            #pragma unroll
            for (int i = 0; i < 4; i++) {
                ulonglong2 tv; tv.x = T[i][0]; tv.y = T[i][1];
                *(ulonglong2*)&s_T[(v0 + i) * 64 + g0] = tv;
            }
            __syncthreads();

            u64 S[4][2];
            #pragma unroll
            for (int i = 0; i < 4; i++) { S[i][0] = 0ull; S[i][1] = 0ull; }
            #pragma unroll 4
            for (int u = 0; u < 64; u++) {
                ulonglong2 tp = *(const ulonglong2*)&s_T[u * 64 + g0];
                float4 av = *(const float4*)&s_aT[u * 68 + v0];
                u64 a;
                a = pk2(av.x, av.x); fma2(S[0][0], a, tp.x); fma2(S[0][1], a, tp.y);
                a = pk2(av.y, av.y); fma2(S[1][0], a, tp.x); fma2(S[1][1], a, tp.y);
                a = pk2(av.z, av.z); fma2(S[2][0], a, tp.x); fma2(S[2][1], a, tp.y);
                a = pk2(av.w, av.w); fma2(S[3][0], a, tp.x); fma2(S[3][1], a, tp.y);
            }
            float x[4][4];
            #pragma unroll
            for (int i = 0; i < 4; i++) {
                ulonglong2 e = *(const ulonglong2*)&s_et[(v0 + i) * 64 + g0];
                add2(G[i][0], S[i][0]); add2(G[i][1], S[i][1]);
                add2(G[i][0], e.x);     add2(G[i][1], e.y);
                up2(G[i][0], x[i][0], x[i][1]);
                up2(G[i][1], x[i][2], x[i][3]);
                x[i][0] = fmaxf(x[i][0], 0.f); x[i][1] = fmaxf(x[i][1], 0.f);
                x[i][2] = fmaxf(x[i][2], 0.f); x[i][3] = fmaxf(x[i][3], 0.f);
            }
            #pragma unroll
            for (int j = 0; j < 4; j++) {
                float4 old = *(const float4*)&s_hT[(g0 + j) * 68 + v0];
                float4 nv;
                nv.x = (mk[0] != 0.f) ? x[0][j] : old.x;
                nv.y = (mk[1] != 0.f) ? x[1][j] : old.y;
                nv.z = (mk[2] != 0.f) ? x[2][j] : old.z;
                nv.w = (mk[3] != 0.f) ? x[3][j] : old.w;
                *(float4*)&s_hT[(g0 + j) * 68 + v0] = nv;
            }
            __syncthreads();
        }

        // ---- readout (identical to R7) ----
        for (int i4 = tid; i4 < 2048; i4 += 256) {
            *(float4*)&s_W  [i4 * 4] = *(const float4*)&W_r[i4 * 4];
            *(float4*)&s_Wrb[i4 * 4] = *(const float4*)&W_r[8192 + i4 * 4];
        }
        for (int i4 = tid; i4 < 1024; i4 += 256) {
            int v = i4 >> 4, f = (i4 & 15) * 4;
            float4 nv = *(const float4*)&nb[v * 64 + f];
            s_nT[(f + 0) * 68 + v] = nv.x;
            s_nT[(f + 1) * 68 + v] = nv.y;
            s_nT[(f + 2) * 68 + v] = nv.z;
            s_nT[(f + 3) * 68 + v] = nv.w;
        }
        __syncthreads();

        u64 acc[8][2];
        {
            ulonglong2 br = *(const ulonglong2*)&b_r[o0];
            #pragma unroll
            for (int vv = 0; vv < 8; vv++) { acc[vv][0] = br.x; acc[vv][1] = br.y; }
        }
        #pragma unroll 2
        for (int k = 0; k < 64; k++) {
            ulonglong2 q = *(const ulonglong2*)&s_W[k * 128 + o0];
            float4 h0 = *(const float4*)&s_hT[k * 68 + v0r];
            float4 h1 = *(const float4*)&s_hT[k * 68 + v0r + 4];
            u64 hp;
            hp = pk2(h0.x, h0.x); fma2(acc[0][0], hp, q.x); fma2(acc[0][1], hp, q.y);
            hp = pk2(h0.y, h0.y); fma2(acc[1][0], hp, q.x); fma2(acc[1][1], hp, q.y);
            hp = pk2(h0.z, h0.z); fma2(acc[2][0], hp, q.x); fma2(acc[2][1], hp, q.y);
            hp = pk2(h0.w, h0.w); fma2(acc[3][0], hp, q.x); fma2(acc[3][1], hp, q.y);
            hp = pk2(h1.x, h1.x); fma2(acc[4][0], hp, q.x); fma2(acc[4][1], hp, q.y);
            hp = pk2(h1.y, h1.y); fma2(acc[5][0], hp, q.x); fma2(acc[5][1], hp, q.y);
            hp = pk2(h1.z, h1.z); fma2(acc[6][0], hp, q.x); fma2(acc[6][1], hp, q.y);
            hp = pk2(h1.w, h1.w); fma2(acc[7][0], hp, q.x); fma2(acc[7][1], hp, q.y);
        }
        #pragma unroll 2
        for (int k = 0; k < 64; k++) {
            ulonglong2 q = *(const ulonglong2*)&s_Wrb[k * 128 + o0];
            float4 n0 = *(const float4*)&s_nT[k * 68 + v0r];
            float4 n1 = *(const float4*)&s_nT[k * 68 + v0r + 4];
            u64 hp;
            hp = pk2(n0.x, n0.x); fma2(acc[0][0], hp, q.x); fma2(acc[0][1], hp, q.y);
            hp = pk2(n0.y, n0.y); fma2(acc[1][0], hp, q.x); fma2(acc[1][1], hp, q.y);
            hp = pk2(n0.z, n0.z); fma2(acc[2][0], hp, q.x); fma2(acc[2][1], hp, q.y);
            hp = pk2(n0.w, n0.w); fma2(acc[3][0], hp, q.x); fma2(acc[3][1], hp, q.y);
            hp = pk2(n1.x, n1.x); fma2(acc[4][0], hp, q.x); fma2(acc[4][1], hp, q.y);
            hp = pk2(n1.y, n1.y); fma2(acc[5][0], hp, q.x); fma2(acc[5][1], hp, q.y);
            hp = pk2(n1.z, n1.z); fma2(acc[6][0], hp, q.x); fma2(acc[6][1], hp, q.y);
            hp = pk2(n1.w, n1.w); fma2(acc[7][0], hp, q.x); fma2(acc[7][1], hp, q.y);
        }
        float oa[4] = {0.f, 0.f, 0.f, 0.f};
        #pragma unroll
        for (int vv = 0; vv < 8; vv++) {
            if (s_mask[v0r + vv] != 0.f) {
                float y0, y1, y2, y3;
                up2(acc[vv][0], y0, y1); up2(acc[vv][1], y2, y3);
                oa[0] += fmaxf(y0, 0.f); oa[1] += fmaxf(y1, 0.f);
                oa[2] += fmaxf(y2, 0.f); oa[3] += fmaxf(y3, 0.f);
            }
        }
        __syncthreads();
        *(float4*)&s_red[ry * 128 + o0] = make_float4(oa[0], oa[1], oa[2], oa[3]);
        __syncthreads();
        if (tid < 128) {
            float s = 0.f;
            #pragma unroll
            for (int t = 0; t < 8; t++) s += s_red[t * 128 + tid];
            out[b * 128 + tid] = s;
        }
        __syncthreads();
    }
}

// ---------------------------------------------------------------------------
// Launch
// ---------------------------------------------------------------------------
extern "C" void kernel_launch(void* const* d_in, const int* in_sizes, int n_in,
                              void* d_out, int out_size)
{
    const int*   adj   = (const int*)  d_in[0];
    const float* nodes = (const float*)d_in[1];
    const float* edges = (const float*)d_in[2];
    const float* W_n   = (const float*)d_in[3];
    const float* W_e   = (const float*)d_in[4];
    const float* b_m   = (const float*)d_in[5];
    const float* W_u   = (const float*)d_in[6];
    const float* b_u   = (const float*)d_in[7];
    const float* W_r   = (const float*)d_in[8];
    const float* b_r   = (const float*)d_in[9];
    float* out = (float*)d_out;

    cudaFuncSetAttribute(k_mpnn, cudaFuncAttributeMaxDynamicSharedMemorySize,
                         SMEM_BYTES);

    k_fold<<<9, 256>>>(W_n, W_e, b_m, W_u, b_u);
    k_mpnn<<<296, 256, SMEM_BYTES>>>(adj, nodes, edges, W_u, W_r, b_r, out);
}